// round 8
// baseline (speedup 1.0000x reference)
#include <cuda_runtime.h>
#include <cstdint>
#include <cstddef>

// HugeNet: 10000 x (Linear(100,100)+ReLU) scan, then Linear(100,10).
//
// Round 8: TWO independent 128-thread "engines" per CTA, each owning 2
// batch rows and synchronized by its OWN named barrier (bar.sync 1|2,128).
// Warps 0-3 = engine A, warps 4-7 = engine B -> every SMSP hosts one warp
// of each engine; when A stalls on its barrier/LDS/FMA chain, B issues.
// Each engine: one output column per thread (j = thread-in-engine, <100
// live), full k in registers, NO reduction (no shfl, no smem partials),
// one named barrier per layer. W double-buffered in registers, streamed
// from a thread-interleaved gmem layout. 64 CTAs x (2+2) rows.

#define N_LAYERS 10000
#define D        100
#define D_OUT    10
#define BATCH    256
#define NCTA     64
#define THREADS  256
#define QUADS    25               // float4 per thread per layer (100 k)
#define ETHR     128              // threads per engine

typedef unsigned long long ull;

// [(N_LAYERS+1)][QUADS][128] float4 (~512MB, zero-padded)
__device__ __align__(16) float4 g_Wp[(size_t)(N_LAYERS + 1) * QUADS * ETHR];

// ---------------------------------------------------------------------------
// prep: W[l][j][k] row-major -> g_Wp[(l*QUADS + q)*128 + t], j = t, k = 4q
// ---------------------------------------------------------------------------
__global__ void prep_kernel(const float* __restrict__ W) {
    size_t idx = (size_t)blockIdx.x * blockDim.x + threadIdx.x;
    const size_t total = (size_t)(N_LAYERS + 1) * QUADS * ETHR;
    if (idx >= total) return;
    int    t    = (int)(idx & (ETHR - 1));
    size_t rest = idx >> 7;
    int    q    = (int)(rest % QUADS);
    size_t l    = rest / QUADS;
    float4 v = make_float4(0.f, 0.f, 0.f, 0.f);
    if (l < N_LAYERS && t < D)
        v = *reinterpret_cast<const float4*>(
                W + l * (size_t)(D * D) + (size_t)t * D + 4 * q);
    g_Wp[idx] = v;
}

// ---------------------------------------------------------------------------
__device__ __forceinline__ void fma2(ull& a, ull x, ull y) {
    asm("fma.rn.f32x2 %0, %1, %2, %0;" : "+l"(a) : "l"(x), "l"(y));
}
__device__ __forceinline__ float2 upk(ull v) {
    float2 r;
    asm("mov.b64 {%0, %1}, %2;" : "=f"(r.x), "=f"(r.y) : "l"(v));
    return r;
}
__device__ __forceinline__ void barrier_engine(int eng) {
    asm volatile("bar.sync %0, 128;" :: "r"(eng + 1) : "memory");
}

__global__ void __launch_bounds__(THREADS, 1)
hugenet_kernel(const float* __restrict__ x,
               const float* __restrict__ bg,
               const float* __restrict__ Wo,
               const float* __restrict__ bo,
               float* __restrict__ out) {
    // [engine][buf][row][col], 104 stride keeps rows 16B-aligned
    __shared__ float h[2][2][2][104];

    const int tid  = threadIdx.x;
    const int eng  = tid >> 7;          // 0: warps 0-3, 1: warps 4-7
    const int et   = tid & (ETHR - 1);  // thread within engine
    const int j    = et;                // output column (j<100 live)
    const bool live = (j < D);
    const int r0   = blockIdx.x * 4;    // 4 rows per CTA, 2 per engine

    // whole CTA loads x: rows r0..r0+3 -> engine (rr>>1), row (rr&1)
    for (int idx = tid; idx < 4 * D; idx += THREADS) {
        int rr = idx / D, k = idx % D;
        h[rr >> 1][0][rr & 1][k] = x[(size_t)(r0 + rr) * D + k];
    }
    __syncthreads();

    float4 Wa[QUADS], Wb[QUADS];
    float  ba = 0.f, bb = 0.f;

    auto ldW = [&](float4* R, int l) {
        const float4* p = g_Wp + (size_t)l * QUADS * ETHR + et;
        #pragma unroll
        for (int q = 0; q < QUADS; q++)
            R[q] = __ldg(p + (size_t)q * ETHR);
    };
    auto ldB = [&](float& b, int l) {
        if (live && l < N_LAYERS) b = __ldg(bg + (size_t)l * D + j);
    };

    int hb = 0;
    auto do_layer = [&](const float4* R, float bias) {
        ull a0 = 0ull, a1 = 0ull, a2 = 0ull, a3 = 0ull;
        const float* h0 = h[eng][hb][0];
        const float* h1 = h[eng][hb][1];
        #pragma unroll
        for (int q = 0; q < QUADS; q++) {
            ulonglong2 w  = *reinterpret_cast<const ulonglong2*>(&R[q]);
            ulonglong2 v0 = *reinterpret_cast<const ulonglong2*>(h0 + 4 * q);
            ulonglong2 v1 = *reinterpret_cast<const ulonglong2*>(h1 + 4 * q);
            fma2(a0, v0.x, w.x);
            fma2(a1, v0.y, w.y);
            fma2(a2, v1.x, w.x);
            fma2(a3, v1.y, w.y);
        }
        float2 u0 = upk(a0), u1 = upk(a1), u2 = upk(a2), u3 = upk(a3);
        float s0 = (u0.x + u1.x) + (u0.y + u1.y) + bias;
        float s1 = (u2.x + u3.x) + (u2.y + u3.y) + bias;
        if (live) {
            h[eng][hb ^ 1][0][j] = fmaxf(s0, 0.f);
            h[eng][hb ^ 1][1][j] = fmaxf(s1, 0.f);
        }
        barrier_engine(eng);
        hb ^= 1;
    };

    ldW(Wa, 0);
    ldB(ba, 0);

    #pragma unroll 1
    for (int l = 0; l < N_LAYERS; l += 2) {
        ldW(Wb, l + 1);                 // prefetch next layer (full hiding)
        ldB(bb, l + 1);

        do_layer(Wa, ba);               // layer l

        ldW(Wa, l + 2);                 // l+2 == N_LAYERS reads zero pad
        ldB(ba, l + 2);

        do_layer(Wb, bb);               // layer l+1
    }

    // After 10000 layers hb == 0 -> h in buf 0. Final Linear(100,10):
    // per engine, 20 threads handle (row, out-col).
    if (et < 2 * D_OUT) {
        int r = et / D_OUT, o = et % D_OUT;
        const float* hr = h[eng][0][r];
        float acc = bo[o];
        #pragma unroll
        for (int k = 0; k < D; k++)
            acc += hr[k] * __ldg(&Wo[(size_t)o * D + k]);
        out[(size_t)(r0 + eng * 2 + r) * D_OUT + o] = acc;
    }
}

// ---------------------------------------------------------------------------
extern "C" void kernel_launch(void* const* d_in, const int* in_sizes, int n_in,
                              void* d_out, int out_size) {
    const float *x = nullptr, *W = nullptr, *b = nullptr, *Wo = nullptr, *bo = nullptr;
    for (int i = 0; i < n_in; i++) {
        switch (in_sizes[i]) {
            case 25600:     x  = (const float*)d_in[i]; break;
            case 100000000: W  = (const float*)d_in[i]; break;
            case 1000000:   b  = (const float*)d_in[i]; break;
            case 1000:      Wo = (const float*)d_in[i]; break;
            case 10:        bo = (const float*)d_in[i]; break;
            default: break;
        }
    }

    const size_t total = (size_t)(N_LAYERS + 1) * QUADS * ETHR;
    int blocks = (int)((total + 255) / 256);
    prep_kernel<<<blocks, 256>>>(W);

    hugenet_kernel<<<NCTA, THREADS>>>(x, b, Wo, bo, (float*)d_out);
}